// round 16
// baseline (speedup 1.0000x reference)
#include <cuda_runtime.h>
#include <cuda_fp16.h>
#include <math.h>

#define NN 100000
#define NE 1600000
#define IN_DIM 128
#define HID 64
#define OUTD 40
#define NB ((NN + 255) / 256)   // 391 scan chunks

// Scratch — __device__ globals (no allocation APIs allowed).
// g_Ah holds dinv[r]*h[r]; row NN is a zero sentinel (never written; device
// globals are zero-initialized; padding lanes read it for a 0 contribution).
__device__ __half2 g_Ah[(NN + 1) * 32];
__device__ __half2 g_Bh[NN * 32];    // conv-1 output in fp16 (feeds gemm2)
__device__ int     g_deg[NN];
__device__ float   g_dinv[NN];
__device__ int     g_off[NN];        // local chunk offsets; inclusive end after fill
__device__ int     g_bsum[512];      // scanned chunk sums
__device__ int     g_csr_src[NE];    // CSR: src only (norm factored out)
__device__ int     g_scan_ctr;       // last-block election (reset after use)

// Per-block edge dtype detection: sample 32 odd 32-bit words from the first
// 2048 words (safe for both dtypes). int64 indices < 2^31 => all high words 0.
__device__ __forceinline__ int detect_is64(const int* ei32) {
    __shared__ int s64;
    if (threadIdx.x < 32) {
        int v = ei32[2 * threadIdx.x + 1];
        unsigned m = __ballot_sync(0xffffffffu, v == 0);
        if (threadIdx.x == 0) s64 = (m == 0xffffffffu) ? 1 : 0;
    }
    __syncthreads();
    return s64;
}

// ---------------- Degree count: 2 edges per thread, dst only ----------------
__global__ void deg_kernel(const void* __restrict__ ei) {
    const int* ei32 = (const int*)ei;
    int is64 = detect_is64(ei32);
    int e2 = blockIdx.x * blockDim.x + threadIdx.x;
    if (e2 >= NE / 2) return;
    int d0, d1;
    if (is64) {
        longlong2 dp = *(const longlong2*)((const long long*)ei + NE + 2 * (size_t)e2);
        d0 = (int)dp.x; d1 = (int)dp.y;
    } else {
        int2 dp = *(const int2*)(ei32 + NE + 2 * (size_t)e2);
        d0 = dp.x; d1 = dp.y;
    }
    if ((unsigned)d0 < NN) atomicAdd(&g_deg[d0], 1);
    if ((unsigned)d1 < NN) atomicAdd(&g_deg[d1], 1);
}

// ---------------- Fused scan: per-chunk scan + last-block chunk-sum scan ----------------
__global__ void scan_fused() {
    __shared__ int sh[256];
    __shared__ int isLast;
    int t = threadIdx.x, i = blockIdx.x * 256 + t;
    int v = (i < NN) ? g_deg[i] : 0;
    if (i < NN) g_dinv[i] = rsqrtf((float)v + 1.0f);  // +1 = self-loop
    sh[t] = v;
    __syncthreads();
    for (int off = 1; off < 256; off <<= 1) {
        int x = (t >= off) ? sh[t - off] : 0;
        __syncthreads();
        sh[t] += x;
        __syncthreads();
    }
    if (i < NN) g_off[i] = sh[t] - v;
    if (t == 255) g_bsum[blockIdx.x] = sh[255];

    // Elect last block
    __threadfence();
    if (t == 0) isLast = (atomicAdd(&g_scan_ctr, 1) == gridDim.x - 1) ? 1 : 0;
    __syncthreads();
    if (!isLast) return;
    __threadfence();

    // Warp 0 scans the NB chunk sums (NB=391 <= 32*32): lane handles 32 entries.
    if (t < 32) {
        int base = t * 32;
        int vals[32];
        int run = 0;
#pragma unroll
        for (int k = 0; k < 32; k++) {
            int idx = base + k;
            int x = (idx < NB) ? g_bsum[idx] : 0;
            vals[k] = run;
            run += x;
        }
        int inc = run;
        for (int o = 1; o < 32; o <<= 1) {
            int x = __shfl_up_sync(0xffffffffu, inc, o);
            if (t >= o) inc += x;
        }
        int offs = inc - run;
#pragma unroll
        for (int k = 0; k < 32; k++) {
            int idx = base + k;
            if (idx < NB) g_bsum[idx] = vals[k] + offs;
        }
    }
    if (t == 0) g_scan_ctr = 0;   // reset for next graph replay
}

// ---------------- Fill: 2 edges per thread, src-only CSR ----------------
__global__ void fill_kernel(const void* __restrict__ ei) {
    const int* ei32 = (const int*)ei;
    int is64 = detect_is64(ei32);
    int e2 = blockIdx.x * blockDim.x + threadIdx.x;
    if (e2 >= NE / 2) return;
    int s0, s1, d0, d1;
    if (is64) {
        longlong2 sp = *(const longlong2*)((const long long*)ei + 2 * (size_t)e2);
        longlong2 dp = *(const longlong2*)((const long long*)ei + NE + 2 * (size_t)e2);
        s0 = (int)sp.x; s1 = (int)sp.y; d0 = (int)dp.x; d1 = (int)dp.y;
    } else {
        int2 sp = *(const int2*)(ei32 + 2 * (size_t)e2);
        int2 dp = *(const int2*)(ei32 + NE + 2 * (size_t)e2);
        s0 = sp.x; s1 = sp.y; d0 = dp.x; d1 = dp.y;
    }
    if ((unsigned)s0 < NN && (unsigned)d0 < NN) {
        int pos = g_bsum[d0 >> 8] + atomicAdd(&g_off[d0], 1);
        g_csr_src[pos] = s0;
    }
    if ((unsigned)s1 < NN && (unsigned)d1 < NN) {
        int pos = g_bsum[d1 >> 8] + atomicAdd(&g_off[d1], 1);
        g_csr_src[pos] = s1;
    }
}

// ---------------- ldmatrix helpers ----------------
__device__ __forceinline__ void ldsm_x4(unsigned& r0, unsigned& r1, unsigned& r2, unsigned& r3,
                                        const void* p) {
    unsigned addr = (unsigned)__cvta_generic_to_shared(p);
    asm volatile("ldmatrix.sync.aligned.m8n8.x4.shared.b16 {%0,%1,%2,%3}, [%4];"
                 : "=r"(r0), "=r"(r1), "=r"(r2), "=r"(r3) : "r"(addr));
}
__device__ __forceinline__ void ldsm_x4t(unsigned& r0, unsigned& r1, unsigned& r2, unsigned& r3,
                                         const void* p) {
    unsigned addr = (unsigned)__cvta_generic_to_shared(p);
    asm volatile("ldmatrix.sync.aligned.m8n8.x4.trans.shared.b16 {%0,%1,%2,%3}, [%4];"
                 : "=r"(r0), "=r"(r1), "=r"(r2), "=r"(r3) : "r"(addr));
}

#define MMA_STEP(cN, A0, A1, A2, A3, B0, B1)                                     \
    asm volatile(                                                                \
        "mma.sync.aligned.m16n8k16.row.col.f32.f16.f16.f32 "                     \
        "{%0,%1,%2,%3}, {%4,%5,%6,%7}, {%8,%9}, {%0,%1,%2,%3};"                  \
        : "+f"(cN[0]), "+f"(cN[1]), "+f"(cN[2]), "+f"(cN[3])                     \
        : "r"(A0), "r"(A1), "r"(A2), "r"(A3), "r"(B0), "r"(B1))

// ---------------- GEMM 1: g_Ah[M,64] = dinv * (x[M,128] @ W1) ----------------
// 256 threads (8 warps), 128-row tile; dinv folded into the epilogue.

__global__ __launch_bounds__(256) void gemm_tc1(
    const float* __restrict__ X, const float* __restrict__ W, int M)
{
    constexpr int K = IN_DIM, LDA = K + 8, LDB = 64 + 8;
    extern __shared__ __half smem1[];
    __half* As = smem1;                 // [128][LDA]
    __half* Ws = smem1 + 128 * LDA;     // [K][LDB]
    const int tid = threadIdx.x;
    const int r0 = blockIdx.x * 128;

    for (int i = tid; i < K * 16; i += 256) {
        int k = i >> 4, n4 = (i & 15) * 4;
        float4 wv = *(const float4*)&W[(size_t)k * 64 + n4];
        *(__half2*)&Ws[k * LDB + n4]     = __floats2half2_rn(wv.x, wv.y);
        *(__half2*)&Ws[k * LDB + n4 + 2] = __floats2half2_rn(wv.z, wv.w);
    }
#pragma unroll
    for (int bat = 0; bat < 2; bat++) {
        float4 v[8];
#pragma unroll
        for (int u = 0; u < 8; u++) {
            int f = tid + (bat * 8 + u) * 256;
            int r = f >> 5, c4 = f & 31;
            int gr = r0 + r;
            v[u] = (gr < M) ? __ldg((const float4*)&X[(size_t)gr * K + c4 * 4])
                            : make_float4(0.f, 0.f, 0.f, 0.f);
        }
#pragma unroll
        for (int u = 0; u < 8; u++) {
            int f = tid + (bat * 8 + u) * 256;
            int r = f >> 5, c4 = f & 31;
            *(__half2*)&As[r * LDA + c4 * 4]     = __floats2half2_rn(v[u].x, v[u].y);
            *(__half2*)&As[r * LDA + c4 * 4 + 2] = __floats2half2_rn(v[u].z, v[u].w);
        }
    }
    __syncthreads();

    const int w = tid >> 5;
    const int T = tid & 31;
    const int qr = T >> 2, qc = T & 3;
    const int arow = w * 16 + (T & 15);
    const int acol = ((T >> 4) & 1) * 8;
    const int krow_off = (T & 7) + ((T >> 3) & 1) * 8;
    const int ncol_half = ((T >> 4) & 1) * 8;

    float c[8][4];
#pragma unroll
    for (int n = 0; n < 8; n++)
#pragma unroll
        for (int j = 0; j < 4; j++) c[n][j] = 0.f;

#pragma unroll
    for (int ks = 0; ks < K / 16; ks++) {
        unsigned a0, a1, a2, a3;
        ldsm_x4(a0, a1, a2, a3, &As[arow * LDA + ks * 16 + acol]);
        unsigned bb[16];
#pragma unroll
        for (int p = 0; p < 4; p++)
            ldsm_x4t(bb[4 * p], bb[4 * p + 1], bb[4 * p + 2], bb[4 * p + 3],
                     &Ws[(ks * 16 + krow_off) * LDB + p * 16 + ncol_half]);
#pragma unroll
        for (int n = 0; n < 8; n++) MMA_STEP(c[n], a0, a1, a2, a3, bb[2 * n], bb[2 * n + 1]);
    }

    const int row0 = r0 + w * 16 + qr;
    float s0 = (row0 < M) ? g_dinv[row0] : 0.f;
    float s1 = (row0 + 8 < M) ? g_dinv[row0 + 8] : 0.f;
#pragma unroll
    for (int n = 0; n < 8; n++) {
        int cidx = n * 4 + qc;
        if (row0 < M)
            g_Ah[(size_t)row0 * 32 + cidx] = __floats2half2_rn(c[n][0] * s0, c[n][1] * s0);
        if (row0 + 8 < M)
            g_Ah[(size_t)(row0 + 8) * 32 + cidx] = __floats2half2_rn(c[n][2] * s1, c[n][3] * s1);
    }
}

// ---------------- GEMM 2: g_Ah[M,64] = dinv * (g_Bh[M,64] @ W2) ----------------

__global__ __launch_bounds__(128) void gemm_tc2(const float* __restrict__ W, int M)
{
    constexpr int K = HID, LDA = K + 8, LDB = 64 + 8;
    __shared__ __half As[64 * LDA];
    __shared__ __half Ws[K * LDB];
    const int tid = threadIdx.x;
    const int r0 = blockIdx.x * 64;

    for (int i = tid; i < K * 16; i += 128) {
        int k = i >> 4, n4 = (i & 15) * 4;
        float4 wv = *(const float4*)&W[(size_t)k * 64 + n4];
        *(__half2*)&Ws[k * LDB + n4]     = __floats2half2_rn(wv.x, wv.y);
        *(__half2*)&Ws[k * LDB + n4 + 2] = __floats2half2_rn(wv.z, wv.w);
    }
#pragma unroll
    for (int u = 0; u < 4; u++) {
        int i = tid + u * 128;
        int r = i >> 3, c8 = i & 7;
        int gr = r0 + r;
        uint4 xv = (gr < M) ? *(const uint4*)&g_Bh[(size_t)gr * 32 + c8 * 4]
                            : make_uint4(0u, 0u, 0u, 0u);
        *(uint4*)&As[r * LDA + c8 * 8] = xv;
    }
    __syncthreads();

    const int w = tid >> 5;
    const int T = tid & 31;
    const int qr = T >> 2, qc = T & 3;
    const int arow = w * 16 + (T & 15);
    const int acol = ((T >> 4) & 1) * 8;
    const int krow_off = (T & 7) + ((T >> 3) & 1) * 8;
    const int ncol_half = ((T >> 4) & 1) * 8;

    float c[8][4];
#pragma unroll
    for (int n = 0; n < 8; n++)
#pragma unroll
        for (int j = 0; j < 4; j++) c[n][j] = 0.f;

#pragma unroll
    for (int ks = 0; ks < K / 16; ks++) {
        unsigned a0, a1, a2, a3;
        ldsm_x4(a0, a1, a2, a3, &As[arow * LDA + ks * 16 + acol]);
        unsigned bb[16];
#pragma unroll
        for (int p = 0; p < 4; p++)
            ldsm_x4t(bb[4 * p], bb[4 * p + 1], bb[4 * p + 2], bb[4 * p + 3],
                     &Ws[(ks * 16 + krow_off) * LDB + p * 16 + ncol_half]);
#pragma unroll
        for (int n = 0; n < 8; n++) MMA_STEP(c[n], a0, a1, a2, a3, bb[2 * n], bb[2 * n + 1]);
    }

    const int row0 = r0 + w * 16 + qr;
    float s0 = (row0 < M) ? g_dinv[row0] : 0.f;
    float s1 = (row0 + 8 < M) ? g_dinv[row0 + 8] : 0.f;
#pragma unroll
    for (int n = 0; n < 8; n++) {
        int cidx = n * 4 + qc;
        if (row0 < M)
            g_Ah[(size_t)row0 * 32 + cidx] = __floats2half2_rn(c[n][0] * s0, c[n][1] * s0);
        if (row0 + 8 < M)
            g_Ah[(size_t)(row0 + 8) * 32 + cidx] = __floats2half2_rn(c[n][2] * s1, c[n][3] * s1);
    }
}

// ---------------- Gather (+ optional fused head) ----------------
// out_row = (Σ_edges g_Ah[src] + g_Ah[node]) * dinv[node] + b.
// Row loads in zero-padded groups of 8 (MLP=8); sentinel src = NN (zero row).

template <bool HEAD>
__global__ __launch_bounds__(256) void gather_kernel(
    const float* __restrict__ b, int relu,
    const float* __restrict__ Wl, const float* __restrict__ bl,
    float* __restrict__ out)
{
    __shared__ float Wls[HEAD ? 64 * OUTD : 1];
    __shared__ float bls[HEAD ? OUTD : 1];
    __shared__ float rowS[HEAD ? 8 : 1][64];

    const int tid = threadIdx.x;
    if (HEAD) {
        for (int i = tid; i < 64 * OUTD; i += 256) Wls[i] = Wl[i];
        if (tid < OUTD) bls[tid] = bl[tid];
        __syncthreads();
    }

    int node = (blockIdx.x * blockDim.x + tid) >> 5;
    int lane = tid & 31;
    if (node >= NN) return;

    int end = g_bsum[node >> 8] + g_off[node];   // inclusive end after fill
    int j0 = end - g_deg[node];

    float a0 = 0.f, a1 = 0.f;

    for (int base = j0; base < end; base += 32) {
        int rem = end - base;
        int meta = NN;                           // sentinel zero row
        if (lane < rem) meta = __ldg(&g_csr_src[base + lane]);
        int cnt = rem < 32 ? rem : 32;
        int nGrp = (cnt + 7) >> 3;
        for (int g = 0; g < nGrp; g++) {
            int i = g * 8;
            float2 v[8];
#pragma unroll
            for (int u = 0; u < 8; u++) {
                int s = __shfl_sync(0xffffffffu, meta, i + u);
                v[u] = __half22float2(g_Ah[(size_t)s * 32 + lane]);
            }
#pragma unroll
            for (int u = 0; u < 8; u++) {
                a0 += v[u].x;
                a1 += v[u].y;
            }
        }
    }

    // self-loop row + final scale
    float2 vs = __half22float2(g_Ah[(size_t)node * 32 + lane]);
    float di = g_dinv[node];
    a0 = (a0 + vs.x) * di + b[2 * lane];
    a1 = (a1 + vs.y) * di + b[2 * lane + 1];

    if (!HEAD) {
        if (relu) { a0 = fmaxf(a0, 0.f); a1 = fmaxf(a1, 0.f); }
        g_Bh[(size_t)node * 32 + lane] = __floats2half2_rn(a0, a1);
        return;
    }

    const int w = tid >> 5;
    rowS[w][2 * lane] = a0;
    rowS[w][2 * lane + 1] = a1;
    __syncwarp();

    float acc0 = bls[lane];
    float acc1 = (lane < 8) ? bls[32 + lane] : 0.f;
#pragma unroll
    for (int k = 0; k < 64; k++) {
        float ek = rowS[w][k];
        acc0 = fmaf(ek, Wls[k * OUTD + lane], acc0);
        if (lane < 8) acc1 = fmaf(ek, Wls[k * OUTD + 32 + lane], acc1);
    }

    float m = acc0;
    if (lane < 8) m = fmaxf(m, acc1);
#pragma unroll
    for (int off = 16; off; off >>= 1) m = fmaxf(m, __shfl_xor_sync(0xffffffffu, m, off));
    float sum = expf(acc0 - m) + ((lane < 8) ? expf(acc1 - m) : 0.f);
#pragma unroll
    for (int off = 16; off; off >>= 1) sum += __shfl_xor_sync(0xffffffffu, sum, off);
    float lse = m + logf(sum);

    out[(size_t)node * OUTD + lane] = acc0 - lse;
    if (lane < 8) out[(size_t)node * OUTD + 32 + lane] = acc1 - lse;
}

// ---------------- Launch ----------------

extern "C" void kernel_launch(void* const* d_in, const int* in_sizes, int n_in,
                              void* d_out, int out_size)
{
    const float* x  = (const float*)d_in[0];
    const void*  ei = d_in[1];
    const float* W1 = (const float*)d_in[2];
    const float* b1 = (const float*)d_in[3];
    const float* W2 = (const float*)d_in[4];
    const float* b2 = (const float*)d_in[5];
    const float* Wl = (const float*)d_in[6];
    const float* bl = (const float*)d_in[7];
    float* out = (float*)d_out;

    const int M = NN;
    const int E2BLK = (NE / 2 + 255) / 256;
    constexpr int GEMM1_SMEM = (128 * (IN_DIM + 8) + IN_DIM * 72) * 2;  // 53248 B

    cudaFuncSetAttribute(gemm_tc1, cudaFuncAttributeMaxDynamicSharedMemorySize, GEMM1_SMEM);

    void* degp;
    cudaGetSymbolAddress(&degp, g_deg);
    cudaMemsetAsync(degp, 0, NN * sizeof(int));

    // CSR build (3 kernels); gemm1 lands at profiled launch index 3.
    deg_kernel<<<E2BLK, 256>>>(ei);
    scan_fused<<<NB, 256>>>();
    fill_kernel<<<E2BLK, 256>>>(ei);

    // Layer 1
    gemm_tc1<<<(M + 127) / 128, 256, GEMM1_SMEM>>>(x, W1, M);
    gather_kernel<false><<<(M * 32 + 255) / 256, 256>>>(b1, 1, nullptr, nullptr, nullptr);

    // Layer 2 + fused head
    gemm_tc2<<<(M + 63) / 64, 128>>>(W2, M);
    gather_kernel<true><<<(M * 32 + 255) / 256, 256>>>(b2, 0, Wl, bl, out);
}

// round 17
// speedup vs baseline: 1.4807x; 1.4807x over previous
#include <cuda_runtime.h>
#include <cuda_fp16.h>
#include <math.h>

#define NN 100000
#define NE 1600000
#define IN_DIM 128
#define HID 64
#define OUTD 40
#define NB ((NN + 255) / 256)   // 391 scan chunks

// Scratch — __device__ globals (no allocation APIs allowed).
// g_Ah holds dinv[r]*h[r]; row NN is a zero sentinel (never written; device
// globals are zero-initialized; padding lanes read it for a 0 contribution).
__device__ __half2 g_Ah[(NN + 1) * 32];
__device__ __half2 g_Bh[NN * 32];    // conv-1 output in fp16 (feeds gemm2)
__device__ int     g_deg[NN];
__device__ float   g_dinv[NN];
__device__ int     g_off[NN];        // local chunk offsets; inclusive end after fill
__device__ int     g_bsum[512];      // scanned chunk sums
__device__ int     g_csr_src[NE];    // CSR: src only (norm factored out)
__device__ int     g_scan_ctr;       // last-block election (reset after use)

// Per-block edge dtype detection: sample 32 odd 32-bit words from the first
// 2048 words (safe for both dtypes). int64 indices < 2^31 => all high words 0.
__device__ __forceinline__ int detect_is64(const int* ei32) {
    __shared__ int s64;
    if (threadIdx.x < 32) {
        int v = ei32[2 * threadIdx.x + 1];
        unsigned m = __ballot_sync(0xffffffffu, v == 0);
        if (threadIdx.x == 0) s64 = (m == 0xffffffffu) ? 1 : 0;
    }
    __syncthreads();
    return s64;
}

// ---------------- Degree count: 2 edges per thread, dst only ----------------
__global__ void deg_kernel(const void* __restrict__ ei) {
    const int* ei32 = (const int*)ei;
    int is64 = detect_is64(ei32);
    int e2 = blockIdx.x * blockDim.x + threadIdx.x;
    if (e2 >= NE / 2) return;
    int d0, d1;
    if (is64) {
        longlong2 dp = *(const longlong2*)((const long long*)ei + NE + 2 * (size_t)e2);
        d0 = (int)dp.x; d1 = (int)dp.y;
    } else {
        int2 dp = *(const int2*)(ei32 + NE + 2 * (size_t)e2);
        d0 = dp.x; d1 = dp.y;
    }
    if ((unsigned)d0 < NN) atomicAdd(&g_deg[d0], 1);
    if ((unsigned)d1 < NN) atomicAdd(&g_deg[d1], 1);
}

// ---------------- Fused scan: per-chunk scan + last-block chunk-sum scan ----------------
__global__ void scan_fused() {
    __shared__ int sh[256];
    __shared__ int isLast;
    int t = threadIdx.x, i = blockIdx.x * 256 + t;
    int v = (i < NN) ? g_deg[i] : 0;
    if (i < NN) g_dinv[i] = rsqrtf((float)v + 1.0f);  // +1 = self-loop
    sh[t] = v;
    __syncthreads();
    for (int off = 1; off < 256; off <<= 1) {
        int x = (t >= off) ? sh[t - off] : 0;
        __syncthreads();
        sh[t] += x;
        __syncthreads();
    }
    if (i < NN) g_off[i] = sh[t] - v;
    if (t == 255) g_bsum[blockIdx.x] = sh[255];

    // Elect last block
    __threadfence();
    if (t == 0) isLast = (atomicAdd(&g_scan_ctr, 1) == gridDim.x - 1) ? 1 : 0;
    __syncthreads();
    if (!isLast) return;
    __threadfence();

    // Warp 0 scans the NB chunk sums (NB=391 <= 32*32): lane handles 32 entries.
    if (t < 32) {
        int base = t * 32;
        int vals[32];
        int run = 0;
#pragma unroll
        for (int k = 0; k < 32; k++) {
            int idx = base + k;
            int x = (idx < NB) ? g_bsum[idx] : 0;
            vals[k] = run;
            run += x;
        }
        int inc = run;
        for (int o = 1; o < 32; o <<= 1) {
            int x = __shfl_up_sync(0xffffffffu, inc, o);
            if (t >= o) inc += x;
        }
        int offs = inc - run;
#pragma unroll
        for (int k = 0; k < 32; k++) {
            int idx = base + k;
            if (idx < NB) g_bsum[idx] = vals[k] + offs;
        }
    }
    if (t == 0) g_scan_ctr = 0;   // reset for next graph replay
}

// ---------------- Fill: 2 edges per thread, src-only CSR ----------------
__global__ void fill_kernel(const void* __restrict__ ei) {
    const int* ei32 = (const int*)ei;
    int is64 = detect_is64(ei32);
    int e2 = blockIdx.x * blockDim.x + threadIdx.x;
    if (e2 >= NE / 2) return;
    int s0, s1, d0, d1;
    if (is64) {
        longlong2 sp = *(const longlong2*)((const long long*)ei + 2 * (size_t)e2);
        longlong2 dp = *(const longlong2*)((const long long*)ei + NE + 2 * (size_t)e2);
        s0 = (int)sp.x; s1 = (int)sp.y; d0 = (int)dp.x; d1 = (int)dp.y;
    } else {
        int2 sp = *(const int2*)(ei32 + 2 * (size_t)e2);
        int2 dp = *(const int2*)(ei32 + NE + 2 * (size_t)e2);
        s0 = sp.x; s1 = sp.y; d0 = dp.x; d1 = dp.y;
    }
    if ((unsigned)s0 < NN && (unsigned)d0 < NN) {
        int pos = g_bsum[d0 >> 8] + atomicAdd(&g_off[d0], 1);
        g_csr_src[pos] = s0;
    }
    if ((unsigned)s1 < NN && (unsigned)d1 < NN) {
        int pos = g_bsum[d1 >> 8] + atomicAdd(&g_off[d1], 1);
        g_csr_src[pos] = s1;
    }
}

// ---------------- ldmatrix helpers ----------------
__device__ __forceinline__ void ldsm_x4(unsigned& r0, unsigned& r1, unsigned& r2, unsigned& r3,
                                        const void* p) {
    unsigned addr = (unsigned)__cvta_generic_to_shared(p);
    asm volatile("ldmatrix.sync.aligned.m8n8.x4.shared.b16 {%0,%1,%2,%3}, [%4];"
                 : "=r"(r0), "=r"(r1), "=r"(r2), "=r"(r3) : "r"(addr));
}
__device__ __forceinline__ void ldsm_x4t(unsigned& r0, unsigned& r1, unsigned& r2, unsigned& r3,
                                         const void* p) {
    unsigned addr = (unsigned)__cvta_generic_to_shared(p);
    asm volatile("ldmatrix.sync.aligned.m8n8.x4.trans.shared.b16 {%0,%1,%2,%3}, [%4];"
                 : "=r"(r0), "=r"(r1), "=r"(r2), "=r"(r3) : "r"(addr));
}

#define MMA_STEP(cN, A0, A1, A2, A3, B0, B1)                                     \
    asm volatile(                                                                \
        "mma.sync.aligned.m16n8k16.row.col.f32.f16.f16.f32 "                     \
        "{%0,%1,%2,%3}, {%4,%5,%6,%7}, {%8,%9}, {%0,%1,%2,%3};"                  \
        : "+f"(cN[0]), "+f"(cN[1]), "+f"(cN[2]), "+f"(cN[3])                     \
        : "r"(A0), "r"(A1), "r"(A2), "r"(A3), "r"(B0), "r"(B1))

// ---------------- GEMM 1: g_Ah[M,64] = dinv * (x[M,128] @ W1) ----------------
// 256 threads (8 warps), 128-row tile; dinv folded into the epilogue.

__global__ __launch_bounds__(256) void gemm_tc1(
    const float* __restrict__ X, const float* __restrict__ W, int M)
{
    constexpr int K = IN_DIM, LDA = K + 8, LDB = 64 + 8;
    extern __shared__ __half smem1[];
    __half* As = smem1;                 // [128][LDA]
    __half* Ws = smem1 + 128 * LDA;     // [K][LDB]
    const int tid = threadIdx.x;
    const int r0 = blockIdx.x * 128;

    for (int i = tid; i < K * 16; i += 256) {
        int k = i >> 4, n4 = (i & 15) * 4;
        float4 wv = *(const float4*)&W[(size_t)k * 64 + n4];
        *(__half2*)&Ws[k * LDB + n4]     = __floats2half2_rn(wv.x, wv.y);
        *(__half2*)&Ws[k * LDB + n4 + 2] = __floats2half2_rn(wv.z, wv.w);
    }
#pragma unroll
    for (int bat = 0; bat < 2; bat++) {
        float4 v[8];
#pragma unroll
        for (int u = 0; u < 8; u++) {
            int f = tid + (bat * 8 + u) * 256;
            int r = f >> 5, c4 = f & 31;
            int gr = r0 + r;
            v[u] = (gr < M) ? __ldg((const float4*)&X[(size_t)gr * K + c4 * 4])
                            : make_float4(0.f, 0.f, 0.f, 0.f);
        }
#pragma unroll
        for (int u = 0; u < 8; u++) {
            int f = tid + (bat * 8 + u) * 256;
            int r = f >> 5, c4 = f & 31;
            *(__half2*)&As[r * LDA + c4 * 4]     = __floats2half2_rn(v[u].x, v[u].y);
            *(__half2*)&As[r * LDA + c4 * 4 + 2] = __floats2half2_rn(v[u].z, v[u].w);
        }
    }
    __syncthreads();

    const int w = tid >> 5;
    const int T = tid & 31;
    const int qr = T >> 2, qc = T & 3;
    const int arow = w * 16 + (T & 15);
    const int acol = ((T >> 4) & 1) * 8;
    const int krow_off = (T & 7) + ((T >> 3) & 1) * 8;
    const int ncol_half = ((T >> 4) & 1) * 8;

    float c[8][4];
#pragma unroll
    for (int n = 0; n < 8; n++)
#pragma unroll
        for (int j = 0; j < 4; j++) c[n][j] = 0.f;

#pragma unroll
    for (int ks = 0; ks < K / 16; ks++) {
        unsigned a0, a1, a2, a3;
        ldsm_x4(a0, a1, a2, a3, &As[arow * LDA + ks * 16 + acol]);
        unsigned bb[16];
#pragma unroll
        for (int p = 0; p < 4; p++)
            ldsm_x4t(bb[4 * p], bb[4 * p + 1], bb[4 * p + 2], bb[4 * p + 3],
                     &Ws[(ks * 16 + krow_off) * LDB + p * 16 + ncol_half]);
#pragma unroll
        for (int n = 0; n < 8; n++) MMA_STEP(c[n], a0, a1, a2, a3, bb[2 * n], bb[2 * n + 1]);
    }

    const int row0 = r0 + w * 16 + qr;
    float s0 = (row0 < M) ? g_dinv[row0] : 0.f;
    float s1 = (row0 + 8 < M) ? g_dinv[row0 + 8] : 0.f;
#pragma unroll
    for (int n = 0; n < 8; n++) {
        int cidx = n * 4 + qc;
        if (row0 < M)
            g_Ah[(size_t)row0 * 32 + cidx] = __floats2half2_rn(c[n][0] * s0, c[n][1] * s0);
        if (row0 + 8 < M)
            g_Ah[(size_t)(row0 + 8) * 32 + cidx] = __floats2half2_rn(c[n][2] * s1, c[n][3] * s1);
    }
}

// ---------------- GEMM 2: g_Ah[M,64] = dinv * (g_Bh[M,64] @ W2) ----------------

__global__ __launch_bounds__(128) void gemm_tc2(const float* __restrict__ W, int M)
{
    constexpr int K = HID, LDA = K + 8, LDB = 64 + 8;
    __shared__ __half As[64 * LDA];
    __shared__ __half Ws[K * LDB];
    const int tid = threadIdx.x;
    const int r0 = blockIdx.x * 64;

    for (int i = tid; i < K * 16; i += 128) {
        int k = i >> 4, n4 = (i & 15) * 4;
        float4 wv = *(const float4*)&W[(size_t)k * 64 + n4];
        *(__half2*)&Ws[k * LDB + n4]     = __floats2half2_rn(wv.x, wv.y);
        *(__half2*)&Ws[k * LDB + n4 + 2] = __floats2half2_rn(wv.z, wv.w);
    }
#pragma unroll
    for (int u = 0; u < 4; u++) {
        int i = tid + u * 128;
        int r = i >> 3, c8 = i & 7;
        int gr = r0 + r;
        uint4 xv = (gr < M) ? *(const uint4*)&g_Bh[(size_t)gr * 32 + c8 * 4]
                            : make_uint4(0u, 0u, 0u, 0u);
        *(uint4*)&As[r * LDA + c8 * 8] = xv;
    }
    __syncthreads();

    const int w = tid >> 5;
    const int T = tid & 31;
    const int qr = T >> 2, qc = T & 3;
    const int arow = w * 16 + (T & 15);
    const int acol = ((T >> 4) & 1) * 8;
    const int krow_off = (T & 7) + ((T >> 3) & 1) * 8;
    const int ncol_half = ((T >> 4) & 1) * 8;

    float c[8][4];
#pragma unroll
    for (int n = 0; n < 8; n++)
#pragma unroll
        for (int j = 0; j < 4; j++) c[n][j] = 0.f;

#pragma unroll
    for (int ks = 0; ks < K / 16; ks++) {
        unsigned a0, a1, a2, a3;
        ldsm_x4(a0, a1, a2, a3, &As[arow * LDA + ks * 16 + acol]);
        unsigned bb[16];
#pragma unroll
        for (int p = 0; p < 4; p++)
            ldsm_x4t(bb[4 * p], bb[4 * p + 1], bb[4 * p + 2], bb[4 * p + 3],
                     &Ws[(ks * 16 + krow_off) * LDB + p * 16 + ncol_half]);
#pragma unroll
        for (int n = 0; n < 8; n++) MMA_STEP(c[n], a0, a1, a2, a3, bb[2 * n], bb[2 * n + 1]);
    }

    const int row0 = r0 + w * 16 + qr;
    float s0 = (row0 < M) ? g_dinv[row0] : 0.f;
    float s1 = (row0 + 8 < M) ? g_dinv[row0 + 8] : 0.f;
#pragma unroll
    for (int n = 0; n < 8; n++) {
        int cidx = n * 4 + qc;
        if (row0 < M)
            g_Ah[(size_t)row0 * 32 + cidx] = __floats2half2_rn(c[n][0] * s0, c[n][1] * s0);
        if (row0 + 8 < M)
            g_Ah[(size_t)(row0 + 8) * 32 + cidx] = __floats2half2_rn(c[n][2] * s1, c[n][3] * s1);
    }
}

// ---------------- Gather (+ optional fused head) ----------------
// out_row = (Σ_edges g_Ah[src] + g_Ah[node]) * dinv[node] + b.
// Row loads in zero-padded groups of 8 (MLP=8); sentinel src = NN (zero row).

template <bool HEAD>
__global__ __launch_bounds__(256) void gather_kernel(
    const float* __restrict__ b, int relu,
    const float* __restrict__ Wl, const float* __restrict__ bl,
    float* __restrict__ out)
{
    __shared__ float Wls[HEAD ? 64 * OUTD : 1];
    __shared__ float bls[HEAD ? OUTD : 1];
    __shared__ float rowS[HEAD ? 8 : 1][64];

    const int tid = threadIdx.x;
    if (HEAD) {
        for (int i = tid; i < 64 * OUTD; i += 256) Wls[i] = Wl[i];
        if (tid < OUTD) bls[tid] = bl[tid];
        __syncthreads();
    }

    int node = (blockIdx.x * blockDim.x + tid) >> 5;
    int lane = tid & 31;
    if (node >= NN) return;

    int end = g_bsum[node >> 8] + g_off[node];   // inclusive end after fill
    int j0 = end - g_deg[node];

    float a0 = 0.f, a1 = 0.f;

    for (int base = j0; base < end; base += 32) {
        int rem = end - base;
        int meta = NN;                           // sentinel zero row
        if (lane < rem) meta = __ldg(&g_csr_src[base + lane]);
        int cnt = rem < 32 ? rem : 32;
        int nGrp = (cnt + 7) >> 3;
        for (int g = 0; g < nGrp; g++) {
            int i = g * 8;
            float2 v[8];
#pragma unroll
            for (int u = 0; u < 8; u++) {
                int s = __shfl_sync(0xffffffffu, meta, i + u);
                v[u] = __half22float2(__ldg(&g_Ah[(size_t)s * 32 + lane]));
            }
#pragma unroll
            for (int u = 0; u < 8; u++) {
                a0 += v[u].x;
                a1 += v[u].y;
            }
        }
    }

    // self-loop row + final scale
    float2 vs = __half22float2(__ldg(&g_Ah[(size_t)node * 32 + lane]));
    float di = g_dinv[node];
    a0 = (a0 + vs.x) * di + b[2 * lane];
    a1 = (a1 + vs.y) * di + b[2 * lane + 1];

    if (!HEAD) {
        if (relu) { a0 = fmaxf(a0, 0.f); a1 = fmaxf(a1, 0.f); }
        g_Bh[(size_t)node * 32 + lane] = __floats2half2_rn(a0, a1);
        return;
    }

    const int w = tid >> 5;
    rowS[w][2 * lane] = a0;
    rowS[w][2 * lane + 1] = a1;
    __syncwarp();

    float acc0 = bls[lane];
    float acc1 = (lane < 8) ? bls[32 + lane] : 0.f;
#pragma unroll
    for (int k = 0; k < 64; k++) {
        float ek = rowS[w][k];
        acc0 = fmaf(ek, Wls[k * OUTD + lane], acc0);
        if (lane < 8) acc1 = fmaf(ek, Wls[k * OUTD + 32 + lane], acc1);
    }

    float m = acc0;
    if (lane < 8) m = fmaxf(m, acc1);
#pragma unroll
    for (int off = 16; off; off >>= 1) m = fmaxf(m, __shfl_xor_sync(0xffffffffu, m, off));
    float sum = expf(acc0 - m) + ((lane < 8) ? expf(acc1 - m) : 0.f);
#pragma unroll
    for (int off = 16; off; off >>= 1) sum += __shfl_xor_sync(0xffffffffu, sum, off);
    float lse = m + logf(sum);

    out[(size_t)node * OUTD + lane] = acc0 - lse;
    if (lane < 8) out[(size_t)node * OUTD + 32 + lane] = acc1 - lse;
}

// ---------------- Launch ----------------

extern "C" void kernel_launch(void* const* d_in, const int* in_sizes, int n_in,
                              void* d_out, int out_size)
{
    const float* x  = (const float*)d_in[0];
    const void*  ei = d_in[1];
    const float* W1 = (const float*)d_in[2];
    const float* b1 = (const float*)d_in[3];
    const float* W2 = (const float*)d_in[4];
    const float* b2 = (const float*)d_in[5];
    const float* Wl = (const float*)d_in[6];
    const float* bl = (const float*)d_in[7];
    float* out = (float*)d_out;

    const int M = NN;
    const int E2BLK = (NE / 2 + 255) / 256;
    constexpr int GEMM1_SMEM = (128 * (IN_DIM + 8) + IN_DIM * 72) * 2;  // 53248 B

    cudaFuncSetAttribute(gemm_tc1, cudaFuncAttributeMaxDynamicSharedMemorySize, GEMM1_SMEM);

    void* degp;
    cudaGetSymbolAddress(&degp, g_deg);
    cudaMemsetAsync(degp, 0, NN * sizeof(int));

    // CSR build (3 kernels); gemm1 lands at profiled launch index 3.
    deg_kernel<<<E2BLK, 256>>>(ei);
    scan_fused<<<NB, 256>>>();
    fill_kernel<<<E2BLK, 256>>>(ei);

    // Layer 1
    gemm_tc1<<<(M + 127) / 128, 256, GEMM1_SMEM>>>(x, W1, M);
    gather_kernel<false><<<(M * 32 + 255) / 256, 256>>>(b1, 1, nullptr, nullptr, nullptr);

    // Layer 2 + fused head
    gemm_tc2<<<(M + 63) / 64, 128>>>(W2, M);
    gather_kernel<true><<<(M * 32 + 255) / 256, 256>>>(b2, 0, Wl, bl, out);
}